// round 13
// baseline (speedup 1.0000x reference)
#include <cuda_runtime.h>
#include <cuda_bf16.h>

// ISTFT: B=8192, F=257 bins, T=6 frames, n_fft=512, hop=128, out len 600.
// CTA = 192 threads = TWO INDEPENDENT 96-thread groups, one batch element
// each (grid 4096). Groups sync only among themselves via named barriers
// (bar.sync 1/2, 96) -- zero cross-element coupling.
// Each warp owns two frames (16 lanes each). irfft-512 = Hermitian half-size
// trick folded into staging -> 256-pt complex inverse FFT via four-step
// 16x16 (register FFTs + pitch-17 shared transpose overlaying the warp's
// own Z region, warp-local syncs). FFT stages 1-2 packed f32x2.
// COLA envelope analytic (1.5 minus edge terms).

#define NT 192
#define FP 272                       // frame region pitch (float2 units)
#define PI_F 3.14159265358979323846f

typedef unsigned long long u64;

__device__ __forceinline__ u64 f2add(u64 a, u64 b) {
    u64 r; asm("add.rn.f32x2 %0,%1,%2;" : "=l"(r) : "l"(a), "l"(b)); return r;
}
__device__ __forceinline__ u64 f2fma(u64 a, u64 b, u64 c) {
    u64 r; asm("fma.rn.f32x2 %0,%1,%2,%3;" : "=l"(r) : "l"(a), "l"(b), "l"(c)); return r;
}
__device__ __forceinline__ u64 f2pk(float lo, float hi) {
    u64 r; asm("mov.b64 %0,{%1,%2};" : "=l"(r) : "f"(lo), "f"(hi)); return r;
}
__device__ __forceinline__ void f2up(u64 v, float& lo, float& hi) {
    asm("mov.b64 {%0,%1},%2;" : "=f"(lo), "=f"(hi) : "l"(v));
}

#define BFLY0(i0,i1) { const float tr=Br[i1], ti=Bi[i1]; \
    Br[i1]=Br[i0]-tr; Bi[i1]=Bi[i0]-ti; Br[i0]+=tr; Bi[i0]+=ti; }
#define BFLYI(i0,i1) { const float tr=-Bi[i1], ti=Br[i1]; \
    Br[i1]=Br[i0]-tr; Bi[i1]=Bi[i0]-ti; Br[i0]+=tr; Bi[i0]+=ti; }
#define BFLYW(i0,i1,cr,ci) { \
    const float vr=Br[i1]*(cr)-Bi[i1]*(ci); \
    const float vi=Br[i1]*(ci)+Bi[i1]*(cr); \
    Br[i1]=Br[i0]-vr; Bi[i1]=Bi[i0]-vi; Br[i0]+=vr; Bi[i0]+=vi; }

// Stages 1-2 of 16-pt inverse DIT FFT on packed (re,im) f32x2 values.
__device__ __forceinline__ void ifft16_head(u64 (&B)[16]) {
    const u64 NEG1 = 0xBF800000BF800000ULL;     // (-1.0f, -1.0f)
    #pragma unroll
    for (int q = 0; q < 16; q += 2) {           // stage 1: all BFLY0
        const u64 v = B[q + 1];
        B[q + 1] = f2fma(v, NEG1, B[q]);
        B[q]     = f2add(B[q], v);
    }
    #pragma unroll
    for (int g = 0; g < 16; g += 4) {           // stage 2
        { const u64 v = B[g + 2];               // BFLY0(g, g+2)
          B[g + 2] = f2fma(v, NEG1, B[g]);
          B[g]     = f2add(B[g], v); }
        { float vr, vi; f2up(B[g + 3], vr, vi); // BFLYI(g+1, g+3): iv = (-vi, vr)
          const u64 iv = f2pk(-vi, vr);
          B[g + 3] = f2fma(iv, NEG1, B[g + 1]);
          B[g + 1] = f2add(B[g + 1], iv); }
    }
}

// Stages 3-4 (scalar, compile-time twiddles). Output natural order.
__device__ __forceinline__ void ifft16_tail(float (&Br)[16], float (&Bi)[16]) {
    const float R  = 0.70710678118654752440f;   // cos(pi/4)
    const float C8 = 0.92387953251128675613f;   // cos(pi/8)
    const float S8 = 0.38268343236508977172f;   // sin(pi/8)
    BFLY0(0,4)  BFLYW(1,5,R,R)   BFLYI(2,6)   BFLYW(3,7,-R,R)
    BFLY0(8,12) BFLYW(9,13,R,R)  BFLYI(10,14) BFLYW(11,15,-R,R)
    BFLY0(0,8)  BFLYW(1,9,C8,S8) BFLYW(2,10,R,R) BFLYW(3,11,S8,C8)
    BFLYI(4,12) BFLYW(5,13,-S8,C8) BFLYW(6,14,-R,R) BFLYW(7,15,-C8,S8)
}

__device__ __forceinline__ int brev4(int v) {
    return ((v & 1) << 3) | ((v & 2) << 1) | ((v & 4) >> 1) | (v >> 3);
}

__device__ __forceinline__ void group_bar(int g) {
    asm volatile("bar.sync %0, 96;" :: "r"(g + 1) : "memory");
}

__global__ __launch_bounds__(NT) void istft_kernel(
    const float* __restrict__ x,   // [B, 1, 257, 6, 2] contiguous
    float* __restrict__ out)       // [B, 1, 600]
{
    const int b2   = blockIdx.x;   // batch-element pair
    const int tid  = threadIdx.x;
    const int lane = tid & 31;
    const int w    = tid >> 5;
    const int sub  = lane >> 4;    // frame-in-warp
    const int L    = lane & 15;
    const int fg   = 2 * w + sub;  // 0..11; element g = fg/6, t = fg%6
    const int g    = (tid >= 96);  // independent half (warps 0-2 / 3-5)
    const int gtid = tid - 96 * g;

    __shared__ __align__(16) float2 pool[12 * FP];

    // ---- phase 1 (group-local): staging + Hermitian half-size combine ----
    // Z[k]=E+iO, Z[256-k]=conj(E-iO) from bin pair (k, 256-k).
    {
        const float4* src = reinterpret_cast<const float4*>(
            x + ((size_t)b2 * 2 + g) * 3084);
        float2* Zb = pool + g * 6 * FP;
        for (int ii = gtid; ii < 387; ii += 96) {
            if (ii < 381) {
                const int k  = ii / 3 + 1;          // 1..127
                const int rr = ii - (k - 1) * 3;
                const float4 A  = src[k * 3 + rr];
                const float4 Bv = src[(256 - k) * 3 + rr];
                float s, c;                          // e^{i*pi*k/256}
                __sincosf((float)k * (PI_F / 256.0f), &s, &c);
                #pragma unroll
                for (int f = 0; f < 2; f++) {
                    const float Xr = f ? A.z : A.x,   Xi = f ? A.w : A.y;
                    const float Yr = f ? Bv.z : Bv.x, Yi = f ? Bv.w : Bv.y;
                    const float Er = 0.5f * (Xr + Yr), Ei = 0.5f * (Xi - Yi);
                    const float Dr = 0.5f * (Xr - Yr), Di = 0.5f * (Xi + Yi);
                    const float Or = Dr * c - Di * s;
                    const float Oi = Dr * s + Di * c;
                    const int tt = 2 * rr + f;
                    Zb[tt * FP + k]       = make_float2(Er - Oi, Ei + Or);
                    Zb[tt * FP + 256 - k] = make_float2(Er + Oi, Or - Ei);
                }
            } else if (ii < 384) {
                const int rr = ii - 381;
                const float4 A  = src[rr];               // bin 0
                const float4 Bv = src[256 * 3 + rr];     // bin 256 (Nyquist)
                Zb[(2 * rr)     * FP] = make_float2(0.5f * (A.x + Bv.x), 0.5f * (A.x - Bv.x));
                Zb[(2 * rr + 1) * FP] = make_float2(0.5f * (A.z + Bv.z), 0.5f * (A.z - Bv.z));
            } else {
                const int rr = ii - 384;
                const float4 A = src[128 * 3 + rr];      // bin 128 self-paired
                Zb[(2 * rr)     * FP + 128] = make_float2(A.x, -A.y);
                Zb[(2 * rr + 1) * FP + 128] = make_float2(A.z, -A.w);
            }
        }
    }
    group_bar(g);

    // ---- phase 2 (warp-local): load Z packed into bit-reversed slots ----
    float2* mine = pool + fg * FP;      // this frame's private 272-float2 region
    const u64* mz = reinterpret_cast<const u64*>(mine);
    u64 B[16];
    #pragma unroll
    for (int s = 0; s < 16; s++)
        B[s] = mz[L + (brev4(s) << 4)];

    // ---- inner 16-pt IFFT: packed stages 1-2, scalar stages 3-4 ----
    ifft16_head(B);
    float Br[16], Bi[16];
    #pragma unroll
    for (int s = 0; s < 16; s++) f2up(B[s], Br[s], Bi[s]);
    ifft16_tail(Br, Bi);

    // ---- four-step twiddle e^{+i*pi*L*k1/128} via recurrence ----
    {
        float wc, ws;
        __sincosf((float)L * (PI_F / 128.0f), &ws, &wc);
        float cc = wc, cs = ws;
        #pragma unroll
        for (int k1 = 1; k1 < 16; k1++) {
            const float br = Br[k1] * cc - Bi[k1] * cs;
            Bi[k1] = Br[k1] * cs + Bi[k1] * cc;
            Br[k1] = br;
            const float nc = cc * wc - cs * ws;
            cs = cc * ws + cs * wc;
            cc = nc;
        }
    }

    // ---- 16x16 transpose, pitch 17, overlaying Z region (warp-local) ----
    __syncwarp();                        // Z reads done before overwrite
    #pragma unroll
    for (int k1 = 0; k1 < 16; k1++)
        mine[L * 17 + k1] = make_float2(Br[k1], Bi[k1]);
    __syncwarp();
    #pragma unroll
    for (int s = 0; s < 16; s++)
        B[s] = mz[brev4(s) * 17 + L];    // row n1=brev4(s), column L

    // ---- outer 16-pt IFFT over n1: slot k2 = X[L + 16*k2] ----
    ifft16_head(B);
    #pragma unroll
    for (int s = 0; s < 16; s++) f2up(B[s], Br[s], Bi[s]);
    ifft16_tail(Br, Bi);

    // ---- store frame buffer (natural order), overlaying scratch ----
    __syncwarp();                        // scratch reads done before overwrite
    #pragma unroll
    for (int k2 = 0; k2 < 16; k2++)
        mine[L + (k2 << 4)] = make_float2(Br[k2], Bi[k2]);
    group_bar(g);

    // ---- paired OLA (group-local): outputs (2m, 2m+1) per iteration ----
    // p = 128q + r (r even); frame q-k contributes float2 at
    // (q-k)*FP + r/2 + 64k = base - (FP-64)k = base - 208k.
    // Hann: cos(pi(r+128k)/256) = {c,-s,-c,s}; odd via angle addition.
    // COLA envelope: w0^2+w1^2+w2^2+w3^2 == 1.5 exactly.
    const float2* fb = pool + g * 6 * FP;
    float* outg = out + ((size_t)b2 * 2 + g) * 600;
    const float cd = 0.99992470183914454093f;   // cos(pi/256)
    const float sd = 0.01227153828571992608f;   // sin(pi/256)
    for (int m = gtid; m < 300; m += 96) {
        const int p = 2 * m + 256;
        const int q = p >> 7;                   // 2..6
        const int r = p & 127;                  // even
        float s, c;
        __sincosf((float)r * (PI_F / 256.0f), &s, &c);
        const float c1 = c * cd - s * sd;
        const float s1 = s * cd + c * sd;
        const float w0 = 0.5f - 0.5f * c,  u0 = 0.5f - 0.5f * c1;
        const float w1 = 0.5f + 0.5f * s,  u1 = 0.5f + 0.5f * s1;
        const float w2 = 0.5f + 0.5f * c,  u2 = 0.5f + 0.5f * c1;
        const float w3 = 0.5f - 0.5f * s,  u3 = 0.5f - 0.5f * s1;
        const int base = q * FP + (r >> 1);

        const float2 v1 = fb[base - 208];
        const float2 v2 = fb[base - 416];
        float acc0 = w1 * v1.x + w2 * v2.x;
        float acc1 = u1 * v1.y + u2 * v2.y;
        float env0 = 1.5f, env1 = 1.5f;
        if (q <= 5) {
            const float2 v0 = fb[base];
            acc0 = fmaf(w0, v0.x, acc0);
            acc1 = fmaf(u0, v0.y, acc1);
        } else {               // k=0 frame missing
            env0 -= w0 * w0; env1 -= u0 * u0;
        }
        if (q >= 3) {
            const float2 v3 = fb[base - 624];
            acc0 = fmaf(w3, v3.x, acc0);
            acc1 = fmaf(u3, v3.y, acc1);
        } else {               // k=3 frame missing
            env0 -= w3 * w3; env1 -= u3 * u3;
        }
        float2 o;
        o.x = __fdividef(acc0, 256.0f * env0);
        o.y = __fdividef(acc1, 256.0f * env1);
        *reinterpret_cast<float2*>(outg + 2 * m) = o;
    }
}

extern "C" void kernel_launch(void* const* d_in, const int* in_sizes, int n_in,
                              void* d_out, int out_size) {
    (void)in_sizes; (void)n_in; (void)out_size;
    const float* x = (const float*)d_in[0];
    float* out = (float*)d_out;
    istft_kernel<<<4096, NT>>>(x, out);
}

// round 14
// speedup vs baseline: 1.1483x; 1.1483x over previous
#include <cuda_runtime.h>
#include <cuda_bf16.h>

// ISTFT: B=8192, F=257 bins, T=6 frames, n_fft=512, hop=128, out len 600.
// ONE batch element per 96-thread CTA (grid 8192): __syncthreads is a cheap
// 3-warp barrier, zero cross-element coupling, ~17 CTAs/SM residency.
// Each warp owns two frames (16 lanes each). irfft-512 = Hermitian half-size
// trick folded into staging -> 256-pt complex inverse FFT via four-step
// 16x16 (register FFTs + pitch-17 shared transpose overlaying the warp's
// own Z region, warp-local syncs). FFT stages 1-2 packed f32x2.
// COLA envelope analytic (1.5 minus edge terms).

#define NT 96
#define FP 272                       // frame region pitch (float2 units)
#define PI_F 3.14159265358979323846f

typedef unsigned long long u64;

__device__ __forceinline__ u64 f2add(u64 a, u64 b) {
    u64 r; asm("add.rn.f32x2 %0,%1,%2;" : "=l"(r) : "l"(a), "l"(b)); return r;
}
__device__ __forceinline__ u64 f2fma(u64 a, u64 b, u64 c) {
    u64 r; asm("fma.rn.f32x2 %0,%1,%2,%3;" : "=l"(r) : "l"(a), "l"(b), "l"(c)); return r;
}
__device__ __forceinline__ u64 f2pk(float lo, float hi) {
    u64 r; asm("mov.b64 %0,{%1,%2};" : "=l"(r) : "f"(lo), "f"(hi)); return r;
}
__device__ __forceinline__ void f2up(u64 v, float& lo, float& hi) {
    asm("mov.b64 {%0,%1},%2;" : "=f"(lo), "=f"(hi) : "l"(v));
}

#define BFLY0(i0,i1) { const float tr=Br[i1], ti=Bi[i1]; \
    Br[i1]=Br[i0]-tr; Bi[i1]=Bi[i0]-ti; Br[i0]+=tr; Bi[i0]+=ti; }
#define BFLYI(i0,i1) { const float tr=-Bi[i1], ti=Br[i1]; \
    Br[i1]=Br[i0]-tr; Bi[i1]=Bi[i0]-ti; Br[i0]+=tr; Bi[i0]+=ti; }
#define BFLYW(i0,i1,cr,ci) { \
    const float vr=Br[i1]*(cr)-Bi[i1]*(ci); \
    const float vi=Br[i1]*(ci)+Bi[i1]*(cr); \
    Br[i1]=Br[i0]-vr; Bi[i1]=Bi[i0]-vi; Br[i0]+=vr; Bi[i0]+=vi; }

// Stages 1-2 of 16-pt inverse DIT FFT on packed (re,im) f32x2 values.
__device__ __forceinline__ void ifft16_head(u64 (&B)[16]) {
    const u64 NEG1 = 0xBF800000BF800000ULL;     // (-1.0f, -1.0f)
    #pragma unroll
    for (int q = 0; q < 16; q += 2) {           // stage 1: all BFLY0
        const u64 v = B[q + 1];
        B[q + 1] = f2fma(v, NEG1, B[q]);
        B[q]     = f2add(B[q], v);
    }
    #pragma unroll
    for (int g = 0; g < 16; g += 4) {           // stage 2
        { const u64 v = B[g + 2];               // BFLY0(g, g+2)
          B[g + 2] = f2fma(v, NEG1, B[g]);
          B[g]     = f2add(B[g], v); }
        { float vr, vi; f2up(B[g + 3], vr, vi); // BFLYI(g+1, g+3): iv = (-vi, vr)
          const u64 iv = f2pk(-vi, vr);
          B[g + 3] = f2fma(iv, NEG1, B[g + 1]);
          B[g + 1] = f2add(B[g + 1], iv); }
    }
}

// Stages 3-4 (scalar, compile-time twiddles). Output natural order.
__device__ __forceinline__ void ifft16_tail(float (&Br)[16], float (&Bi)[16]) {
    const float R  = 0.70710678118654752440f;   // cos(pi/4)
    const float C8 = 0.92387953251128675613f;   // cos(pi/8)
    const float S8 = 0.38268343236508977172f;   // sin(pi/8)
    BFLY0(0,4)  BFLYW(1,5,R,R)   BFLYI(2,6)   BFLYW(3,7,-R,R)
    BFLY0(8,12) BFLYW(9,13,R,R)  BFLYI(10,14) BFLYW(11,15,-R,R)
    BFLY0(0,8)  BFLYW(1,9,C8,S8) BFLYW(2,10,R,R) BFLYW(3,11,S8,C8)
    BFLYI(4,12) BFLYW(5,13,-S8,C8) BFLYW(6,14,-R,R) BFLYW(7,15,-C8,S8)
}

__device__ __forceinline__ int brev4(int v) {
    return ((v & 1) << 3) | ((v & 2) << 1) | ((v & 4) >> 1) | (v >> 3);
}

__global__ __launch_bounds__(NT) void istft_kernel(
    const float* __restrict__ x,   // [B, 1, 257, 6, 2] contiguous
    float* __restrict__ out)       // [B, 1, 600]
{
    const int b    = blockIdx.x;   // batch element
    const int tid  = threadIdx.x;  // 0..95
    const int lane = tid & 31;
    const int w    = tid >> 5;     // 0..2
    const int sub  = lane >> 4;    // frame-in-warp
    const int L    = lane & 15;
    const int fg   = 2 * w + sub;  // frame 0..5

    __shared__ __align__(16) float2 pool[6 * FP];

    // ---- phase 1: staging + Hermitian half-size combine ----
    // Z[k]=E+iO, Z[256-k]=conj(E-iO) from bin pair (k, 256-k).
    {
        const float4* src = reinterpret_cast<const float4*>(x + (size_t)b * 3084);
        for (int ii = tid; ii < 387; ii += NT) {
            if (ii < 381) {
                const int k  = ii / 3 + 1;          // 1..127
                const int rr = ii - (k - 1) * 3;
                const float4 A  = src[k * 3 + rr];
                const float4 Bv = src[(256 - k) * 3 + rr];
                float s, c;                          // e^{i*pi*k/256}
                __sincosf((float)k * (PI_F / 256.0f), &s, &c);
                #pragma unroll
                for (int f = 0; f < 2; f++) {
                    const float Xr = f ? A.z : A.x,   Xi = f ? A.w : A.y;
                    const float Yr = f ? Bv.z : Bv.x, Yi = f ? Bv.w : Bv.y;
                    const float Er = 0.5f * (Xr + Yr), Ei = 0.5f * (Xi - Yi);
                    const float Dr = 0.5f * (Xr - Yr), Di = 0.5f * (Xi + Yi);
                    const float Or = Dr * c - Di * s;
                    const float Oi = Dr * s + Di * c;
                    const int tt = 2 * rr + f;
                    pool[tt * FP + k]       = make_float2(Er - Oi, Ei + Or);
                    pool[tt * FP + 256 - k] = make_float2(Er + Oi, Or - Ei);
                }
            } else if (ii < 384) {
                const int rr = ii - 381;
                const float4 A  = src[rr];               // bin 0
                const float4 Bv = src[256 * 3 + rr];     // bin 256 (Nyquist)
                pool[(2 * rr)     * FP] = make_float2(0.5f * (A.x + Bv.x), 0.5f * (A.x - Bv.x));
                pool[(2 * rr + 1) * FP] = make_float2(0.5f * (A.z + Bv.z), 0.5f * (A.z - Bv.z));
            } else {
                const int rr = ii - 384;
                const float4 A = src[128 * 3 + rr];      // bin 128 self-paired
                pool[(2 * rr)     * FP + 128] = make_float2(A.x, -A.y);
                pool[(2 * rr + 1) * FP + 128] = make_float2(A.z, -A.w);
            }
        }
    }
    __syncthreads();

    // ---- phase 2 (warp-local): load Z packed into bit-reversed slots ----
    float2* mine = pool + fg * FP;      // this frame's private 272-float2 region
    const u64* mz = reinterpret_cast<const u64*>(mine);
    u64 B[16];
    #pragma unroll
    for (int s = 0; s < 16; s++)
        B[s] = mz[L + (brev4(s) << 4)];

    // ---- inner 16-pt IFFT: packed stages 1-2, scalar stages 3-4 ----
    ifft16_head(B);
    float Br[16], Bi[16];
    #pragma unroll
    for (int s = 0; s < 16; s++) f2up(B[s], Br[s], Bi[s]);
    ifft16_tail(Br, Bi);

    // ---- four-step twiddle e^{+i*pi*L*k1/128} via recurrence ----
    {
        float wc, ws;
        __sincosf((float)L * (PI_F / 128.0f), &ws, &wc);
        float cc = wc, cs = ws;
        #pragma unroll
        for (int k1 = 1; k1 < 16; k1++) {
            const float br = Br[k1] * cc - Bi[k1] * cs;
            Bi[k1] = Br[k1] * cs + Bi[k1] * cc;
            Br[k1] = br;
            const float nc = cc * wc - cs * ws;
            cs = cc * ws + cs * wc;
            cc = nc;
        }
    }

    // ---- 16x16 transpose, pitch 17, overlaying Z region (warp-local) ----
    __syncwarp();                        // Z reads done before overwrite
    #pragma unroll
    for (int k1 = 0; k1 < 16; k1++)
        mine[L * 17 + k1] = make_float2(Br[k1], Bi[k1]);
    __syncwarp();
    #pragma unroll
    for (int s = 0; s < 16; s++)
        B[s] = mz[brev4(s) * 17 + L];    // row n1=brev4(s), column L

    // ---- outer 16-pt IFFT over n1: slot k2 = X[L + 16*k2] ----
    ifft16_head(B);
    #pragma unroll
    for (int s = 0; s < 16; s++) f2up(B[s], Br[s], Bi[s]);
    ifft16_tail(Br, Bi);

    // ---- store frame buffer (natural order), overlaying scratch ----
    __syncwarp();                        // scratch reads done before overwrite
    #pragma unroll
    for (int k2 = 0; k2 < 16; k2++)
        mine[L + (k2 << 4)] = make_float2(Br[k2], Bi[k2]);
    __syncthreads();

    // ---- paired OLA: outputs (2m, 2m+1) per iteration ----
    // p = 128q + r (r even); frame q-k contributes float2 at
    // (q-k)*FP + r/2 + 64k = base - (FP-64)k = base - 208k.
    // Hann: cos(pi(r+128k)/256) = {c,-s,-c,s}; odd via angle addition.
    // COLA envelope: w0^2+w1^2+w2^2+w3^2 == 1.5 exactly.
    const float2* fb = pool;
    float* outb = out + (size_t)b * 600;
    const float cd = 0.99992470183914454093f;   // cos(pi/256)
    const float sd = 0.01227153828571992608f;   // sin(pi/256)
    for (int m = tid; m < 300; m += NT) {
        const int p = 2 * m + 256;
        const int q = p >> 7;                   // 2..6
        const int r = p & 127;                  // even
        float s, c;
        __sincosf((float)r * (PI_F / 256.0f), &s, &c);
        const float c1 = c * cd - s * sd;
        const float s1 = s * cd + c * sd;
        const float w0 = 0.5f - 0.5f * c,  u0 = 0.5f - 0.5f * c1;
        const float w1 = 0.5f + 0.5f * s,  u1 = 0.5f + 0.5f * s1;
        const float w2 = 0.5f + 0.5f * c,  u2 = 0.5f + 0.5f * c1;
        const float w3 = 0.5f - 0.5f * s,  u3 = 0.5f - 0.5f * s1;
        const int base = q * FP + (r >> 1);

        const float2 v1 = fb[base - 208];
        const float2 v2 = fb[base - 416];
        float acc0 = w1 * v1.x + w2 * v2.x;
        float acc1 = u1 * v1.y + u2 * v2.y;
        float env0 = 1.5f, env1 = 1.5f;
        if (q <= 5) {
            const float2 v0 = fb[base];
            acc0 = fmaf(w0, v0.x, acc0);
            acc1 = fmaf(u0, v0.y, acc1);
        } else {               // k=0 frame missing
            env0 -= w0 * w0; env1 -= u0 * u0;
        }
        if (q >= 3) {
            const float2 v3 = fb[base - 624];
            acc0 = fmaf(w3, v3.x, acc0);
            acc1 = fmaf(u3, v3.y, acc1);
        } else {               // k=3 frame missing
            env0 -= w3 * w3; env1 -= u3 * u3;
        }
        float2 o;
        o.x = __fdividef(acc0, 256.0f * env0);
        o.y = __fdividef(acc1, 256.0f * env1);
        *reinterpret_cast<float2*>(outb + 2 * m) = o;
    }
}

extern "C" void kernel_launch(void* const* d_in, const int* in_sizes, int n_in,
                              void* d_out, int out_size) {
    (void)in_sizes; (void)n_in; (void)out_size;
    const float* x = (const float*)d_in[0];
    float* out = (float*)d_out;
    istft_kernel<<<8192, NT>>>(x, out);
}